// round 5
// baseline (speedup 1.0000x reference)
#include <cuda_runtime.h>

// EmbeddingRowAdapter: out[t,:] = E[ids[t],:] + (pos[ids[t]]>=0 ? A[pos]·B^T : 0)
// V=100000, D=256, M=8192, R=32, tokens = 204800
// Split design: hot gather kernel (all tokens, high occupancy) + cold delta
// kernel (only adapted tokens, ~8%, Bt in shared with 4-token reuse).

constexpr int D = 256;
constexpr int R = 32;
constexpr int V_MAX = 100000;
constexpr int CAP = 204800;          // max adapted-token list entries

__device__ int   g_pos[V_MAX];       // .bss zero; validated via idx[p]==id
__device__ int   g_is64;
__device__ int   g_count;            // adapted-token count (zeroed in setup)
__device__ int2  g_list[CAP];        // (token t, adapter row p)
__device__ float g_Bt[R][D];         // B transposed: g_Bt[r][d] = Bm[d*R + r]

__device__ __forceinline__ bool detect_is64(const void* idx, int M) {
    return (M > 1) && (((const int*)idx)[1] == 0);
}

// Fused setup: counter reset + B transpose + pos scatter (one launch).
__global__ void setup_kernel(const void* __restrict__ idx,
                             const float* __restrict__ Bm, int M) {
    const int i = blockIdx.x * blockDim.x + threadIdx.x;
    const bool is64 = detect_is64(idx, M);
    if (i == 0) { g_is64 = is64 ? 1 : 0; g_count = 0; }
    if (i < D * R) g_Bt[i & (R - 1)][i >> 5] = Bm[i];   // i = d*R + r
    if (i < M) {
        long long v = is64 ? ((const long long*)idx)[i]
                           : (long long)((const int*)idx)[i];
        if (v >= 0 && v < V_MAX) g_pos[v] = i;
    }
}

// 256-bit E-row load, L2 evict_last (keep E resident vs streaming stores).
__device__ __forceinline__ void ldg256_evict_last(const float* p, float v[8]) {
    unsigned r0, r1, r2, r3, r4, r5, r6, r7;
    asm("ld.global.nc.L2::evict_last.v8.b32 {%0,%1,%2,%3,%4,%5,%6,%7}, [%8];"
        : "=r"(r0), "=r"(r1), "=r"(r2), "=r"(r3),
          "=r"(r4), "=r"(r5), "=r"(r6), "=r"(r7)
        : "l"(p));
    v[0] = __uint_as_float(r0); v[1] = __uint_as_float(r1);
    v[2] = __uint_as_float(r2); v[3] = __uint_as_float(r3);
    v[4] = __uint_as_float(r4); v[5] = __uint_as_float(r5);
    v[6] = __uint_as_float(r6); v[7] = __uint_as_float(r7);
}

// ---- Hot path: base gather for ALL tokens + compaction of adapted ones ----
__global__ __launch_bounds__(128, 8)
void gather_kernel(const void* __restrict__ ids,
                   const void* __restrict__ idx,
                   const float* __restrict__ E,
                   float* __restrict__ out,
                   int n_tokens, int M)
{
    const int lane   = threadIdx.x & 31;
    const int warp   = (blockIdx.x * blockDim.x + threadIdx.x) >> 5;
    const int nwarps = (gridDim.x * blockDim.x) >> 5;
    const int is64   = g_is64;

    for (int t0 = warp * 32; t0 < n_tokens; t0 += nwarps * 32) {
        // Coalesced gather of tile ids + validated pos (one token per lane).
        int tl = t0 + lane;
        int myid = 0, mypos = -1;
        if (tl < n_tokens) {
            long long v = is64 ? ((const long long*)ids)[tl]
                               : (long long)((const int*)ids)[tl];
            myid = (int)v;
            int p = g_pos[myid];
            if (p >= 0 && p < M) {
                long long iv = is64 ? ((const long long*)idx)[p]
                                    : (long long)((const int*)idx)[p];
                if (iv == (long long)myid) mypos = p;
            }
        }

        // Warp-aggregated append of adapted tokens to the global list.
        unsigned m = __ballot_sync(0xffffffffu, mypos >= 0);
        if (m) {
            int leader = __ffs(m) - 1;
            int base = 0;
            if (lane == leader) base = atomicAdd(&g_count, __popc(m));
            base = __shfl_sync(0xffffffffu, base, leader);
            if (mypos >= 0) {
                int slot = base + __popc(m & ((1u << lane) - 1));
                if (slot < CAP) g_list[slot] = make_int2(tl, mypos);
            }
        }

        // Base gather: 4 tokens/iter, one 256-bit E load each (MLP=4).
        const int lim = min(32, n_tokens - t0);
        for (int k = 0; k < lim; k += 4) {
            int id_[4];
            bool have[4];
#pragma unroll
            for (int u = 0; u < 4; u++) {
                have[u] = (k + u) < lim;
                id_[u] = __shfl_sync(0xffffffffu, myid, (k + u) & 31);
            }
            float v[4][8];
#pragma unroll
            for (int u = 0; u < 4; u++)
                if (have[u])
                    ldg256_evict_last(E + (size_t)id_[u] * D + 8 * lane, v[u]);
#pragma unroll
            for (int u = 0; u < 4; u++) {
                if (!have[u]) continue;
                float4* o = reinterpret_cast<float4*>(
                    out + (size_t)(t0 + k + u) * D + 8 * lane);
                __stcs(o,     make_float4(v[u][0], v[u][1], v[u][2], v[u][3]));
                __stcs(o + 1, make_float4(v[u][4], v[u][5], v[u][6], v[u][7]));
            }
        }
    }
}

// ---- Cold path: out[t] += A[p] @ B^T for adapted tokens only --------------
// Bt in shared; each warp does 4 tokens/pass so each Bt LDS serves 4 tokens.
__global__ __launch_bounds__(256)
void delta_kernel(const float* __restrict__ A, float* __restrict__ out)
{
    __shared__ float Bt_s[R][D];     // 32 KB
    for (int i = threadIdx.x; i < R * D / 4; i += blockDim.x)
        reinterpret_cast<float4*>(&Bt_s[0][0])[i] =
            reinterpret_cast<const float4*>(&g_Bt[0][0])[i];
    __syncthreads();

    const int count  = min(g_count, CAP);
    const int lane   = threadIdx.x & 31;
    const int wid    = (blockIdx.x * blockDim.x + threadIdx.x) >> 5;
    const int nwarps = (gridDim.x * blockDim.x) >> 5;

    for (int base = wid * 4; base < count; base += nwarps * 4) {
        const int nb = min(4, count - base);
        int2 e[4];
        bool val[4];
#pragma unroll
        for (int u = 0; u < 4; u++) {
            val[u] = u < nb;
            e[u] = val[u] ? __ldg(&g_list[base + u]) : make_int2(0, 0);
        }

        float acc[4][8];
#pragma unroll
        for (int u = 0; u < 4; u++)
#pragma unroll
            for (int i = 0; i < 8; i++) acc[u][i] = 0.f;

#pragma unroll
        for (int j = 0; j < R / 4; j++) {
            float4 av[4];
#pragma unroll
            for (int u = 0; u < 4; u++)
                if (val[u])
                    av[u] = __ldg(reinterpret_cast<const float4*>(
                                      A + (size_t)e[u].y * R) + j);
#pragma unroll
            for (int rr = 0; rr < 4; rr++) {
                const int r = 4 * j + rr;
                float4 b0 = *reinterpret_cast<const float4*>(&Bt_s[r][8 * lane]);
                float4 b1 = *reinterpret_cast<const float4*>(&Bt_s[r][8 * lane + 4]);
#pragma unroll
                for (int u = 0; u < 4; u++) {
                    if (!val[u]) continue;
                    float a = rr == 0 ? av[u].x : rr == 1 ? av[u].y
                            : rr == 2 ? av[u].z : av[u].w;
                    acc[u][0] = fmaf(a, b0.x, acc[u][0]);
                    acc[u][1] = fmaf(a, b0.y, acc[u][1]);
                    acc[u][2] = fmaf(a, b0.z, acc[u][2]);
                    acc[u][3] = fmaf(a, b0.w, acc[u][3]);
                    acc[u][4] = fmaf(a, b1.x, acc[u][4]);
                    acc[u][5] = fmaf(a, b1.y, acc[u][5]);
                    acc[u][6] = fmaf(a, b1.z, acc[u][6]);
                    acc[u][7] = fmaf(a, b1.w, acc[u][7]);
                }
            }
        }

        // Read-modify-write the output rows.
#pragma unroll
        for (int u = 0; u < 4; u++) {
            if (!val[u]) continue;
            float4* o = reinterpret_cast<float4*>(
                out + (size_t)e[u].x * D + 8 * lane);
            float4 o0 = o[0], o1 = o[1];
            o0.x += acc[u][0]; o0.y += acc[u][1];
            o0.z += acc[u][2]; o0.w += acc[u][3];
            o1.x += acc[u][4]; o1.y += acc[u][5];
            o1.z += acc[u][6]; o1.w += acc[u][7];
            o[0] = o0; o[1] = o1;
        }
    }
}

extern "C" void kernel_launch(void* const* d_in, const int* in_sizes, int n_in,
                              void* d_out, int out_size)
{
    const void*  ids = d_in[0];                 // [B,L] int32 or int64
    const void*  idx = d_in[1];                 // [M]   int32 or int64
    const float* E   = (const float*)d_in[2];   // [V,D]
    const float* A   = (const float*)d_in[3];   // [M,R]
    const float* Bm  = (const float*)d_in[4];   // [D,R]
    float*       out = (float*)d_out;

    const int n_tokens = in_sizes[0];
    const int M        = in_sizes[1];
    const int setup_n  = (M > D * R) ? M : D * R;

    setup_kernel<<<(setup_n + 255) / 256, 256>>>(idx, Bm, M);

    // Gather: 148 SMs x 8 blocks resident = one full wave, grid-stride.
    gather_kernel<<<1184, 128>>>(ids, idx, E, out, n_tokens, M);

    // Delta: grid-stride over the compacted list (count read on device).
    delta_kernel<<<296, 256>>>(A, out);
}

// round 6
// speedup vs baseline: 1.0187x; 1.0187x over previous
#include <cuda_runtime.h>

// EmbeddingRowAdapter: out[t,:] = E[ids[t],:] + (pos[ids[t]]>=0 ? A[pos]·B^T : 0)
// V=100000, D=256, M=8192, R=32, tokens = 204800

constexpr int D = 256;
constexpr int R = 32;
constexpr int V_MAX = 100000;

__device__ int   g_pos[V_MAX];      // .bss zero; validated via idx[p]==id
__device__ int   g_is64;            // 1 if ids/idx stored as int64
__device__ float g_Bt[R][D];        // B transposed: g_Bt[r][d] = Bm[d*R + r]

__device__ __forceinline__ bool detect_is64(const void* idx, int M) {
    return (M > 1) && (((const int*)idx)[1] == 0);
}

// Fused setup: B transpose + pos scatter (one launch).
__global__ void setup_kernel(const void* __restrict__ idx,
                             const float* __restrict__ Bm, int M) {
    const int i = blockIdx.x * blockDim.x + threadIdx.x;
    const bool is64 = detect_is64(idx, M);
    if (i == 0) g_is64 = is64 ? 1 : 0;
    if (i < D * R) g_Bt[i & (R - 1)][i >> 5] = Bm[i];   // i = d*R + r
    if (i < M) {
        long long v = is64 ? ((const long long*)idx)[i]
                           : (long long)((const int*)idx)[i];
        if (v >= 0 && v < V_MAX) g_pos[v] = i;
    }
}

// 256-bit E-row load, L2 evict_last (keep E resident vs streaming stores).
__device__ __forceinline__ void ldg256_evict_last(const float* p, float v[8]) {
    unsigned r0, r1, r2, r3, r4, r5, r6, r7;
    asm("ld.global.nc.L2::evict_last.v8.b32 {%0,%1,%2,%3,%4,%5,%6,%7}, [%8];"
        : "=r"(r0), "=r"(r1), "=r"(r2), "=r"(r3),
          "=r"(r4), "=r"(r5), "=r"(r6), "=r"(r7)
        : "l"(p));
    v[0] = __uint_as_float(r0); v[1] = __uint_as_float(r1);
    v[2] = __uint_as_float(r2); v[3] = __uint_as_float(r3);
    v[4] = __uint_as_float(r4); v[5] = __uint_as_float(r5);
    v[6] = __uint_as_float(r6); v[7] = __uint_as_float(r7);
}

// Shared Bt layout: Bs[r*64 + h*32 + lane] (float4) = Bt[r][8*lane+4*h ..+4).
// Lane stride is 16B -> every 8-lane LDS.128 phase covers all 32 banks once
// (the naive [R][D] layout has a 2-way conflict from its 32B lane stride).
__device__ __forceinline__ void add_delta_smem(float v[8],
                                               const float* __restrict__ A,
                                               const float4* __restrict__ Bs,
                                               int p, int lane) {
    const float4* arow = reinterpret_cast<const float4*>(A + (size_t)p * R);
#pragma unroll
    for (int j = 0; j < R / 4; j++) {
        float4 av = __ldg(arow + j);
        float as[4] = {av.x, av.y, av.z, av.w};
#pragma unroll
        for (int rr = 0; rr < 4; rr++) {
            const int r = 4 * j + rr;
            float4 b0 = Bs[r * 64 + lane];        // d = 8*lane .. +4
            float4 b1 = Bs[r * 64 + 32 + lane];   // d = 8*lane+4 .. +8
            v[0] = fmaf(as[rr], b0.x, v[0]);
            v[1] = fmaf(as[rr], b0.y, v[1]);
            v[2] = fmaf(as[rr], b0.z, v[2]);
            v[3] = fmaf(as[rr], b0.w, v[3]);
            v[4] = fmaf(as[rr], b1.x, v[4]);
            v[5] = fmaf(as[rr], b1.y, v[5]);
            v[6] = fmaf(as[rr], b1.z, v[6]);
            v[7] = fmaf(as[rr], b1.w, v[7]);
        }
    }
}

// One warp per 32-token tile. ids/pos gathered coalesced (lane-per-token,
// validity via idx[p]==id), distributed via shfl. 4 tokens/iter, one 256-bit
// E load each (4 in flight). Delta (warp-uniform, ~8%) reads Bt from smem.
__global__ __launch_bounds__(256, 4)
void adapter_kernel(const void* __restrict__ ids,
                    const void* __restrict__ idx,
                    const float* __restrict__ E,
                    const float* __restrict__ A,
                    float* __restrict__ out,
                    int n_tokens, int M)
{
    __shared__ float4 Bs[R * D / 4];             // 32 KB, permuted layout
    for (int i = threadIdx.x; i < R * D / 4; i += blockDim.x) {
        int r = i >> 6, rem = i & 63;
        int h = rem >> 5, l = rem & 31;
        Bs[i] = *reinterpret_cast<const float4*>(&g_Bt[r][8 * l + 4 * h]);
    }
    __syncthreads();

    const int lane   = threadIdx.x & 31;
    const int warp   = (blockIdx.x * blockDim.x + threadIdx.x) >> 5;
    const int nwarps = (gridDim.x * blockDim.x) >> 5;
    const int is64   = g_is64;

    for (int t0 = warp * 32; t0 < n_tokens; t0 += nwarps * 32) {
        // Coalesced gather of tile ids + validated pos (one token per lane).
        int tl = t0 + lane;
        int myid = 0, mypos = -1;
        if (tl < n_tokens) {
            long long v = is64 ? ((const long long*)ids)[tl]
                               : (long long)((const int*)ids)[tl];
            myid = (int)v;
            int p = g_pos[myid];
            if (p >= 0 && p < M) {
                long long iv = is64 ? ((const long long*)idx)[p]
                                    : (long long)((const int*)idx)[p];
                if (iv == (long long)myid) mypos = p;
            }
        }
        const int lim = min(32, n_tokens - t0);

        for (int k = 0; k < lim; k += 4) {
            int id_[4], p_[4];
            bool have[4];
#pragma unroll
            for (int u = 0; u < 4; u++) {
                have[u] = (k + u) < lim;
                int src = (k + u) & 31;
                id_[u] = __shfl_sync(0xffffffffu, myid,  src);
                p_[u]  = __shfl_sync(0xffffffffu, mypos, src);
            }

            // Batch E loads: one 256-bit ld per token, 4 independent in flight.
            float v[4][8];
#pragma unroll
            for (int u = 0; u < 4; u++)
                if (have[u])
                    ldg256_evict_last(E + (size_t)id_[u] * D + 8 * lane, v[u]);

            // Delta (warp-uniform branch, smem Bt) + streaming stores.
#pragma unroll
            for (int u = 0; u < 4; u++) {
                if (!have[u]) continue;
                if (p_[u] >= 0) add_delta_smem(v[u], A, Bs, p_[u], lane);
                float4* o = reinterpret_cast<float4*>(
                    out + (size_t)(t0 + k + u) * D + 8 * lane);
                __stcs(o,     make_float4(v[u][0], v[u][1], v[u][2], v[u][3]));
                __stcs(o + 1, make_float4(v[u][4], v[u][5], v[u][6], v[u][7]));
            }
        }
    }
}

extern "C" void kernel_launch(void* const* d_in, const int* in_sizes, int n_in,
                              void* d_out, int out_size)
{
    const void*  ids = d_in[0];                 // [B,L] int32 or int64
    const void*  idx = d_in[1];                 // [M]   int32 or int64
    const float* E   = (const float*)d_in[2];   // [V,D]
    const float* A   = (const float*)d_in[3];   // [M,R]
    const float* Bm  = (const float*)d_in[4];   // [D,R]
    float*       out = (float*)d_out;

    const int n_tokens = in_sizes[0];
    const int M        = in_sizes[1];
    const int setup_n  = (M > D * R) ? M : D * R;

    setup_kernel<<<(setup_n + 255) / 256, 256>>>(idx, Bm, M);

    // 6400 tiles; 800 blocks x 8 warps = exactly one 32-token tile per warp.
    int n_tiles  = (n_tokens + 31) / 32;
    int n_blocks = (n_tiles + 7) / 8;
    adapter_kernel<<<n_blocks, 256>>>(ids, idx, E, A, out, n_tokens, M);
}